// round 3
// baseline (speedup 1.0000x reference)
#include <cuda_runtime.h>

// Problem constants
#define NBATCH 8
#define CINCH  256
#define MAPSZ  32
#define HW     1024     // 32*32
#define NHEADS 8
#define DKH    32
#define DVH    32

// Scratch (static device globals — no dynamic allocation allowed)
__device__ float g_q[NBATCH*NHEADS*HW*DKH];     // [n][h][p][d]  8 MB
__device__ float g_k[NBATCH*NHEADS*HW*DKH];     // [n][h][p][d]  8 MB
__device__ float g_v[NBATCH*NHEADS*HW*DVH];     // [n][h][p][d]  8 MB
__device__ float g_attn[NBATCH*256*HW];         // [n][c][Y][X] per reference reshape  8 MB

// ---------------------------------------------------------------------------
// Kernel 1: fused 3x3 conv, 1024 total output channels
//   kind 0: conv_maps -> d_out channels [0,256)
//   kind 1: q  -> g_q,  kind 2: k -> g_k,  kind 3: v -> g_v
// Tile: 2 rows (64 pixels) x 128 channels per block; thread = 4px x 8ch.
// ---------------------------------------------------------------------------
__global__ void __launch_bounds__(256) k_conv(
    const float* __restrict__ x,
    const float* __restrict__ conv_w, const float* __restrict__ conv_b,
    const float* __restrict__ q_w,    const float* __restrict__ q_b,
    const float* __restrict__ k_w,    const float* __restrict__ k_b,
    const float* __restrict__ v_w,    const float* __restrict__ v_b,
    float* __restrict__ out)
{
    __shared__ float xs[8*4*36];     // [ci][yy][xxs]  (xxs = gx+1, padded to 36)
    __shared__ float ws[128*72];     // [cc][ci*9+kk]

    const int tid   = threadIdx.x;
    const int ctile = blockIdx.x;    // 0..7  (128 channels each)
    const int ytile = blockIdx.y;    // 0..15 (2 rows each)
    const int n     = blockIdx.z;
    const int y0    = ytile * 2;

    const int kind = ctile >> 1;     // 0 conv, 1 q, 2 k, 3 v
    const float* wsrc = (kind == 0) ? conv_w : (kind == 1) ? q_w : (kind == 2) ? k_w : v_w;
    const float* bsrc = (kind == 0) ? conv_b : (kind == 1) ? q_b : (kind == 2) ? k_b : v_b;
    const int Cb = (ctile & 1) * 128;

    const int pg = tid & 15;         // pixel group
    const int cg = tid >> 4;         // channel group (8 ch each)

    float acc[8][4];
    #pragma unroll
    for (int u = 0; u < 8; u++)
        #pragma unroll
        for (int j = 0; j < 4; j++) acc[u][j] = 0.f;

    #pragma unroll 1
    for (int c0 = 0; c0 < 256; c0 += 8) {
        __syncthreads();
        // input tile: 8 cin x 4 rows (y0-1..y0+2) x 34 cols (zero halo)
        for (int idx = tid; idx < 8*4*36; idx += 256) {
            int ci = idx / 144, r = idx - ci*144;
            int yy = r / 36,   xxs = r - yy*36;
            int gy = y0 - 1 + yy, gx = xxs - 1;
            float v = 0.f;
            if (gy >= 0 && gy < 32 && gx >= 0 && gx < 32)
                v = x[((n*256 + c0 + ci)*32 + gy)*32 + gx];
            xs[idx] = v;
        }
        // weight tile: 128 out-ch x 8 cin x 9 taps
        for (int e = tid; e < 128*72; e += 256) {
            int cc = e / 72, r = e - cc*72;
            ws[e] = wsrc[((Cb + cc)*256 + c0)*9 + r];
        }
        __syncthreads();

        #pragma unroll 1
        for (int ci = 0; ci < 8; ci++) {
            const float* xr = &xs[ci*144];
            const float* wr = &ws[(cg*8)*72 + ci*9];
            #pragma unroll
            for (int ky = 0; ky < 3; ky++) {
                #pragma unroll
                for (int kx = 0; kx < 3; kx++) {
                    float a0 = xr[ ky   *36 + pg      + kx];
                    float a1 = xr[ ky   *36 + pg + 16 + kx];
                    float a2 = xr[(ky+1)*36 + pg      + kx];
                    float a3 = xr[(ky+1)*36 + pg + 16 + kx];
                    #pragma unroll
                    for (int u = 0; u < 8; u++) {
                        float w = wr[u*72 + ky*3 + kx];
                        acc[u][0] += w*a0; acc[u][1] += w*a1;
                        acc[u][2] += w*a2; acc[u][3] += w*a3;
                    }
                }
            }
        }
    }

    #pragma unroll
    for (int u = 0; u < 8; u++) {
        int c = Cb + cg*8 + u;
        float b = bsrc[c];
        #pragma unroll
        for (int j = 0; j < 4; j++) {
            int row = j >> 1;
            int xx  = pg + ((j & 1) << 4);
            int p   = (y0 + row)*32 + xx;
            float v = acc[u][j] + b;
            if (kind == 0) {
                out[(n*512 + c)*1024 + p] = v;
            } else {
                float* tgt = (kind == 1) ? g_q : (kind == 2) ? g_k : g_v;
                tgt[((n*8 + (c >> 5))*1024 + p)*32 + (c & 31)] = v;
            }
        }
    }
}

// ---------------------------------------------------------------------------
// Kernel 2: flash attention with 2D relative-position bias.
// logit[q=(y,x),k=(ky,kx)] = q.k + q.hm[31+ky-y] + q.wm[31+kx-x], scaled.
// One thread per query; qh/qw (126 precomputed dots per query) in smem [i][t].
//
// Output layout (matches the reference's attn.reshape(N, HEADS*DVH, H, W),
// which interleaves q and d since attn is (N, HEADS, Q, DVH)):
//   g_attn[n][h*32 + y_q][x_q*32 + d] = attn_out[n][h][q=(y_q,x_q)][d]
// ---------------------------------------------------------------------------
#define SM2_FLOATS (2016*2 + 63*128*2 + 128*32*2)   // 28352 floats = 113408 B
__global__ void __launch_bounds__(128) k_attn(
    const float* __restrict__ height_mat, const float* __restrict__ width_mat)
{
    extern __shared__ float sm[];
    float* hm = sm;                  // 63*32
    float* wm = sm + 2016;           // 63*32
    float* qh = sm + 4032;           // 63*128  [i][t]
    float* qw = sm + 12096;          // 63*128
    float* Ks = sm + 20160;          // 128*32
    float* Vs = sm + 24256;          // 128*32

    const int t  = threadIdx.x;
    const int qb = blockIdx.x;       // 0..7
    const int nh = blockIdx.y;       // 0..63
    const int p  = qb*128 + t;
    const int y  = p >> 5, xq = p & 31;

    for (int i = t; i < 2016; i += 128) { hm[i] = height_mat[i]; wm[i] = width_mat[i]; }

    float q[32];
    {
        const float4* qg = (const float4*)(g_q + (nh*1024 + p)*32);
        #pragma unroll
        for (int w = 0; w < 8; w++) {
            float4 v = qg[w];
            q[4*w] = v.x; q[4*w+1] = v.y; q[4*w+2] = v.z; q[4*w+3] = v.w;
        }
    }
    __syncthreads();

    #pragma unroll 1
    for (int i = 0; i < 63; i++) {
        float s0 = 0.f, s1 = 0.f, s2 = 0.f, s3 = 0.f;
        #pragma unroll
        for (int d = 0; d < 32; d += 4) {
            s0 += q[d  ]*hm[i*32+d  ]; s1 += q[d+1]*hm[i*32+d+1];
            s2 += q[d+2]*hm[i*32+d+2]; s3 += q[d+3]*hm[i*32+d+3];
        }
        qh[i*128 + t] = (s0+s1)+(s2+s3);
    }
    #pragma unroll 1
    for (int i = 0; i < 63; i++) {
        float s0 = 0.f, s1 = 0.f, s2 = 0.f, s3 = 0.f;
        #pragma unroll
        for (int d = 0; d < 32; d += 4) {
            s0 += q[d  ]*wm[i*32+d  ]; s1 += q[d+1]*wm[i*32+d+1];
            s2 += q[d+2]*wm[i*32+d+2]; s3 += q[d+3]*wm[i*32+d+3];
        }
        qw[i*128 + t] = (s0+s1)+(s2+s3);
    }

    float m = -1e30f, l = 0.f;
    float acc[32];
    #pragma unroll
    for (int d = 0; d < 32; d++) acc[d] = 0.f;

    const float4* kg = (const float4*)(g_k + nh*1024*32);
    const float4* vg = (const float4*)(g_v + nh*1024*32);

    #pragma unroll 1
    for (int kb = 0; kb < 8; kb++) {
        __syncthreads();
        #pragma unroll
        for (int r = 0; r < 8; r++) {
            ((float4*)Ks)[r*128 + t] = kg[kb*1024 + r*128 + t];
            ((float4*)Vs)[r*128 + t] = vg[kb*1024 + r*128 + t];
        }
        __syncthreads();
        const int kpb = kb*128;
        #pragma unroll 1
        for (int j = 0; j < 128; j++) {
            const int kp = kpb + j;
            const int ky = kp >> 5, kx = kp & 31;
            const float4* kr = (const float4*)(Ks + j*32);
            float s0 = 0.f, s1 = 0.f, s2 = 0.f, s3 = 0.f;
            #pragma unroll
            for (int w = 0; w < 8; w++) {
                float4 kv = kr[w];
                s0 += q[4*w  ]*kv.x; s1 += q[4*w+1]*kv.y;
                s2 += q[4*w+2]*kv.z; s3 += q[4*w+3]*kv.w;
            }
            float s = (s0+s1)+(s2+s3);
            s += qh[(31 + ky - y)*128 + t] + qw[(31 + kx - xq)*128 + t];
            s *= 0.17677669529663687f;   // 1/sqrt(32)

            const float4* vr = (const float4*)(Vs + j*32);
            if (s > m) {
                float corr = __expf(m - s);
                l = l*corr + 1.f;
                #pragma unroll
                for (int w = 0; w < 8; w++) {
                    float4 vv = vr[w];
                    acc[4*w  ] = acc[4*w  ]*corr + vv.x;
                    acc[4*w+1] = acc[4*w+1]*corr + vv.y;
                    acc[4*w+2] = acc[4*w+2]*corr + vv.z;
                    acc[4*w+3] = acc[4*w+3]*corr + vv.w;
                }
                m = s;
            } else {
                float pe = __expf(s - m);
                l += pe;
                #pragma unroll
                for (int w = 0; w < 8; w++) {
                    float4 vv = vr[w];
                    acc[4*w  ] += pe*vv.x;
                    acc[4*w+1] += pe*vv.y;
                    acc[4*w+2] += pe*vv.z;
                    acc[4*w+3] += pe*vv.w;
                }
            }
        }
    }

    const float inv = 1.0f / l;
    const int n = nh >> 3, h = nh & 7;
    // Reference reshape: attn_maps[n][h*32 + y][x*32 + d] = attn[n][h][p=(y,x)][d]
    float* ob = g_attn + (n*256 + h*32 + y)*1024 + xq*32;
    #pragma unroll
    for (int d = 0; d < 32; d++) ob[d] = acc[d]*inv;
}

// ---------------------------------------------------------------------------
// Kernel 3: 1x1 projection of attn maps -> d_out channels [256,512).
// Block: 128 out-ch x 128 pixels; thread = 16ch x 4px.
// ---------------------------------------------------------------------------
__global__ void __launch_bounds__(256) k_proj(
    const float* __restrict__ attn_w, const float* __restrict__ attn_b,
    float* __restrict__ out)
{
    __shared__ float As[32*128];     // [ci][pp]
    __shared__ float Ws[128*32];     // [co][ci]
    const int t = threadIdx.x;
    const int ptile = blockIdx.x;    // 0..7
    const int cotile = blockIdx.y;   // 0..1
    const int n = blockIdx.z;
    const int pg = t & 31, cg = t >> 5;

    float acc[16][4];
    #pragma unroll
    for (int u = 0; u < 16; u++)
        #pragma unroll
        for (int j = 0; j < 4; j++) acc[u][j] = 0.f;

    #pragma unroll 1
    for (int ci0 = 0; ci0 < 256; ci0 += 32) {
        __syncthreads();
        #pragma unroll
        for (int r = 0; r < 16; r++) {
            int e = r*256 + t;
            int ci = e >> 7, pp = e & 127;
            As[e] = g_attn[(n*256 + ci0 + ci)*1024 + ptile*128 + pp];
        }
        #pragma unroll
        for (int r = 0; r < 16; r++) {
            int e = r*256 + t;
            int co = e >> 5, ci = e & 31;
            Ws[e] = attn_w[(cotile*128 + co)*256 + ci0 + ci];
        }
        __syncthreads();
        #pragma unroll 8
        for (int ci = 0; ci < 32; ci++) {
            float a0 = As[ci*128 + pg];
            float a1 = As[ci*128 + pg + 32];
            float a2 = As[ci*128 + pg + 64];
            float a3 = As[ci*128 + pg + 96];
            #pragma unroll
            for (int u = 0; u < 16; u++) {
                float w = Ws[(cg*16 + u)*32 + ci];
                acc[u][0] += w*a0; acc[u][1] += w*a1;
                acc[u][2] += w*a2; acc[u][3] += w*a3;
            }
        }
    }

    #pragma unroll
    for (int u = 0; u < 16; u++) {
        int co = cotile*128 + cg*16 + u;
        float b = attn_b[co];
        #pragma unroll
        for (int j = 0; j < 4; j++) {
            int p = ptile*128 + pg + 32*j;
            out[(n*512 + 256 + co)*1024 + p] = acc[u][j] + b;
        }
    }
}

// ---------------------------------------------------------------------------
extern "C" void kernel_launch(void* const* d_in, const int* in_sizes, int n_in,
                              void* d_out, int out_size)
{
    const float* x          = (const float*)d_in[0];
    const float* conv_w     = (const float*)d_in[1];
    const float* conv_b     = (const float*)d_in[2];
    const float* q_w        = (const float*)d_in[3];
    const float* q_b        = (const float*)d_in[4];
    const float* k_w        = (const float*)d_in[5];
    const float* k_b        = (const float*)d_in[6];
    const float* v_w        = (const float*)d_in[7];
    const float* v_b        = (const float*)d_in[8];
    const float* attn_w     = (const float*)d_in[9];
    const float* attn_b     = (const float*)d_in[10];
    const float* width_mat  = (const float*)d_in[11];
    const float* height_mat = (const float*)d_in[12];
    float* out = (float*)d_out;

    k_conv<<<dim3(8, 16, 8), 256>>>(x, conv_w, conv_b, q_w, q_b,
                                    k_w, k_b, v_w, v_b, out);

    cudaFuncSetAttribute(k_attn, cudaFuncAttributeMaxDynamicSharedMemorySize,
                         SM2_FLOATS * (int)sizeof(float));
    k_attn<<<dim3(8, 64), 128, SM2_FLOATS * sizeof(float)>>>(height_mat, width_mat);

    k_proj<<<dim3(8, 2, 8), 256>>>(attn_w, attn_b, out);
}

// round 5
// speedup vs baseline: 1.4069x; 1.4069x over previous
#include <cuda_runtime.h>

// Problem constants
#define NBATCH 8
#define HW     1024     // 32*32
#define NHEADS 8

// Scratch (static device globals — no dynamic allocation allowed)
__device__ float g_q[NBATCH*NHEADS*HW*32];     // [n][h][p][d]  8 MB
__device__ float g_k[NBATCH*NHEADS*HW*32];     // [n][h][p][d]  8 MB
__device__ float g_v[NBATCH*NHEADS*HW*32];     // [n][h][p][d]  8 MB
__device__ float g_attn[NBATCH*256*HW];        // [n][c][Y][X] per reference reshape

// ---- packed f32x2 helpers (sm_103a FFMA2 path; ptxas won't emit from C++) ----
__device__ __forceinline__ void fma2(unsigned long long& d,
                                     unsigned long long a, unsigned long long b) {
    asm("fma.rn.f32x2 %0, %1, %2, %0;" : "+l"(d) : "l"(a), "l"(b));
}
__device__ __forceinline__ void mul2(unsigned long long& d, unsigned long long a) {
    asm("mul.rn.f32x2 %0, %0, %1;" : "+l"(d) : "l"(a));
}
__device__ __forceinline__ unsigned long long pack2(float lo, float hi) {
    unsigned long long r;
    asm("mov.b64 %0, {%1, %2};" : "=l"(r) : "f"(lo), "f"(hi));
    return r;
}
__device__ __forceinline__ float2 unpack2(unsigned long long v) {
    float2 r;
    asm("mov.b64 {%0, %1}, %2;" : "=f"(r.x), "=f"(r.y) : "l"(v));
    return r;
}

// ---------------------------------------------------------------------------
// Kernel 1: fused 3x3 conv (1024 total out channels) using packed f32x2 FMA.
// Block = 128 threads: 128 co x 64 px (2 rows). Thread = 8 co x 8 px.
//   kind 0: conv_maps -> d_out channels [0,256)
//   kind 1: q -> g_q, kind 2: k -> g_k, kind 3: v -> g_v
// ---------------------------------------------------------------------------
__global__ void __launch_bounds__(128) k_conv(
    const float* __restrict__ x,
    const float* __restrict__ conv_w, const float* __restrict__ conv_b,
    const float* __restrict__ q_w,    const float* __restrict__ q_b,
    const float* __restrict__ k_w,    const float* __restrict__ k_b,
    const float* __restrict__ v_w,    const float* __restrict__ v_b,
    float* __restrict__ out)
{
    __shared__ float xs[8*4*36];     // [ci][iy][xxs]  (xxs = gx+1)
    __shared__ float ws[8*9*128];    // [ci*9+tap][co]  -- co contiguous

    const int t     = threadIdx.x;
    const int ctile = blockIdx.x;    // 0..7  (128 co each)
    const int ytile = blockIdx.y;    // 0..15 (2 rows each)
    const int n     = blockIdx.z;
    const int y0    = ytile * 2;

    const int kind = ctile >> 1;     // 0 conv, 1 q, 2 k, 3 v
    const float* wsrc = (kind == 0) ? conv_w : (kind == 1) ? q_w : (kind == 2) ? k_w : v_w;
    const float* bsrc = (kind == 0) ? conv_b : (kind == 1) ? q_b : (kind == 2) ? k_b : v_b;
    const int Cb = (ctile & 1) * 128;

    const int cg      = t >> 3;          // 0..15 -> co base cg*8
    const int pg      = t & 7;           // 0..7
    const int row_sub = pg >> 2;         // 0..1
    const int x0      = (pg & 3) * 8;    // 0,8,16,24

    unsigned long long acc[8][4];        // [px j][co pair]
    #pragma unroll
    for (int j = 0; j < 8; j++)
        #pragma unroll
        for (int pr = 0; pr < 4; pr++) acc[j][pr] = 0ull;

    #pragma unroll 1
    for (int c0 = 0; c0 < 256; c0 += 8) {
        __syncthreads();
        // x tile: 8 ci x 4 rows (y0-1..y0+2) x 36 (halo + pad), zero padding
        for (int e = t; e < 8*4*36; e += 128) {
            int ci = e / 144, r = e - ci*144;
            int iy = r / 36,  xxs = r - iy*36;
            int gy = y0 - 1 + iy, gx = xxs - 1;
            float v = 0.f;
            if (gy >= 0 && gy < 32 && gx >= 0 && gx < 32)
                v = x[((n*256 + c0 + ci)*32 + gy)*32 + gx];
            xs[e] = v;
        }
        // weights: thread t owns out-channel cc = t; 72 contiguous floats in gmem
        {
            const float4* wp = (const float4*)&wsrc[((Cb + t)*256 + c0)*9];
            #pragma unroll
            for (int i = 0; i < 18; i++) {
                float4 w4 = wp[i];
                ws[(i*4+0)*128 + t] = w4.x;
                ws[(i*4+1)*128 + t] = w4.y;
                ws[(i*4+2)*128 + t] = w4.z;
                ws[(i*4+3)*128 + t] = w4.w;
            }
        }
        __syncthreads();

        #pragma unroll 1
        for (int ci = 0; ci < 8; ci++) {
            const float* xr = &xs[ci*144];
            #pragma unroll
            for (int ky = 0; ky < 3; ky++) {
                const int iy = ky + row_sub;
                unsigned long long a2[10];
                #pragma unroll
                for (int i = 0; i < 10; i++) {
                    float av = xr[iy*36 + x0 + i];
                    a2[i] = pack2(av, av);
                }
                #pragma unroll
                for (int kx = 0; kx < 3; kx++) {
                    const ulonglong2* wq =
                        (const ulonglong2*)&ws[(ci*9 + ky*3 + kx)*128 + cg*8];
                    ulonglong2 wA = wq[0];   // co pairs (0,1),(2,3)
                    ulonglong2 wB = wq[1];   // co pairs (4,5),(6,7)
                    #pragma unroll
                    for (int j = 0; j < 8; j++) {
                        fma2(acc[j][0], wA.x, a2[j+kx]);
                        fma2(acc[j][1], wA.y, a2[j+kx]);
                        fma2(acc[j][2], wB.x, a2[j+kx]);
                        fma2(acc[j][3], wB.y, a2[j+kx]);
                    }
                }
            }
        }
    }

    // epilogue
    const int y = y0 + row_sub;
    #pragma unroll
    for (int pr = 0; pr < 4; pr++) {
        const int c = Cb + cg*8 + pr*2;
        const float b0 = bsrc[c], b1 = bsrc[c+1];
        #pragma unroll
        for (int j = 0; j < 8; j++) {
            const int p = y*32 + x0 + j;
            float2 v = unpack2(acc[j][pr]);
            v.x += b0; v.y += b1;
            if (kind == 0) {
                out[(n*512 + c    )*1024 + p] = v.x;
                out[(n*512 + c + 1)*1024 + p] = v.y;
            } else {
                float* tgt = (kind == 1) ? g_q : (kind == 2) ? g_k : g_v;
                // [n][h][p][d]; c,c+1 share head, consecutive d -> float2 store
                *(float2*)&tgt[((n*8 + (c >> 5))*1024 + p)*32 + (c & 31)] = v;
            }
        }
    }
}

// ---------------------------------------------------------------------------
// Kernel 2: flash attention with 2D relative-position bias (f32x2 FMA).
// logit[q=(y,x),k=(ky,kx)] = q.k + q.hm[31+ky-y] + q.wm[31+kx-x], scaled.
// Output: g_attn[n][h*32 + y_q][x_q*32 + d]  (reference's reshape quirk).
// ---------------------------------------------------------------------------
#define SM2_FLOATS (2016*2 + 63*128*2 + 128*32*2)   // 28352 floats = 113408 B
__global__ void __launch_bounds__(128) k_attn(
    const float* __restrict__ height_mat, const float* __restrict__ width_mat)
{
    extern __shared__ float sm[];
    float* hm = sm;                  // 63*32
    float* wm = sm + 2016;           // 63*32
    float* qh = sm + 4032;           // 63*128  [i][t]
    float* qw = sm + 12096;          // 63*128
    float* Ks = sm + 20160;          // 128*32
    float* Vs = sm + 24256;          // 128*32

    const int t  = threadIdx.x;
    const int qb = blockIdx.x;       // 0..7
    const int nh = blockIdx.y;       // 0..63
    const int p  = qb*128 + t;
    const int y  = p >> 5, xq = p & 31;

    for (int i = t; i < 2016; i += 128) { hm[i] = height_mat[i]; wm[i] = width_mat[i]; }

    float q[32];
    unsigned long long qp[16];       // packed q pairs
    {
        const float4* qg = (const float4*)(g_q + (nh*1024 + p)*32);
        #pragma unroll
        for (int w = 0; w < 8; w++) {
            float4 v = qg[w];
            q[4*w] = v.x; q[4*w+1] = v.y; q[4*w+2] = v.z; q[4*w+3] = v.w;
            qp[2*w]   = pack2(v.x, v.y);
            qp[2*w+1] = pack2(v.z, v.w);
        }
    }
    __syncthreads();

    #pragma unroll 1
    for (int i = 0; i < 63; i++) {
        float s0 = 0.f, s1 = 0.f, s2 = 0.f, s3 = 0.f;
        #pragma unroll
        for (int d = 0; d < 32; d += 4) {
            s0 += q[d  ]*hm[i*32+d  ]; s1 += q[d+1]*hm[i*32+d+1];
            s2 += q[d+2]*hm[i*32+d+2]; s3 += q[d+3]*hm[i*32+d+3];
        }
        qh[i*128 + t] = (s0+s1)+(s2+s3);
    }
    #pragma unroll 1
    for (int i = 0; i < 63; i++) {
        float s0 = 0.f, s1 = 0.f, s2 = 0.f, s3 = 0.f;
        #pragma unroll
        for (int d = 0; d < 32; d += 4) {
            s0 += q[d  ]*wm[i*32+d  ]; s1 += q[d+1]*wm[i*32+d+1];
            s2 += q[d+2]*wm[i*32+d+2]; s3 += q[d+3]*wm[i*32+d+3];
        }
        qw[i*128 + t] = (s0+s1)+(s2+s3);
    }

    float m = -1e30f, l = 0.f;
    unsigned long long vacc[16];
    #pragma unroll
    for (int w = 0; w < 16; w++) vacc[w] = 0ull;

    const float4* kg = (const float4*)(g_k + nh*1024*32);
    const float4* vg = (const float4*)(g_v + nh*1024*32);

    #pragma unroll 1
    for (int kb = 0; kb < 8; kb++) {
        __syncthreads();
        #pragma unroll
        for (int r = 0; r < 8; r++) {
            ((float4*)Ks)[r*128 + t] = kg[kb*1024 + r*128 + t];
            ((float4*)Vs)[r*128 + t] = vg[kb*1024 + r*128 + t];
        }
        __syncthreads();
        const int kpb = kb*128;
        #pragma unroll 1
        for (int j = 0; j < 128; j++) {
            const int kp = kpb + j;
            const int ky = kp >> 5, kx = kp & 31;

            // QK dot: 16 FFMA2
            const ulonglong2* kr = (const ulonglong2*)(Ks + j*32);
            unsigned long long sa = 0ull, sb = 0ull;
            #pragma unroll
            for (int w = 0; w < 8; w++) {
                ulonglong2 kv = kr[w];
                fma2(sa, qp[2*w],   kv.x);
                fma2(sb, qp[2*w+1], kv.y);
            }
            float2 fa = unpack2(sa), fb = unpack2(sb);
            float s = (fa.x + fa.y) + (fb.x + fb.y);
            s += qh[(31 + ky - y)*128 + t] + qw[(31 + kx - xq)*128 + t];
            s *= 0.17677669529663687f;   // 1/sqrt(32)

            float pe;
            if (s > m) {
                float corr = __expf(m - s);
                l = l*corr + 1.f;
                m = s;
                pe = 1.f;
                unsigned long long cd = pack2(corr, corr);
                #pragma unroll
                for (int w = 0; w < 16; w++) mul2(vacc[w], cd);
            } else {
                pe = __expf(s - m);
                l += pe;
            }
            unsigned long long pd = pack2(pe, pe);
            const ulonglong2* vr = (const ulonglong2*)(Vs + j*32);
            #pragma unroll
            for (int w = 0; w < 8; w++) {
                ulonglong2 vv = vr[w];
                fma2(vacc[2*w],   vv.x, pd);
                fma2(vacc[2*w+1], vv.y, pd);
            }
        }
    }

    const float inv = 1.0f / l;
    const int n = nh >> 3, h = nh & 7;
    // attn_maps[n][h*32 + y][x*32 + d]
    float* ob = g_attn + (n*256 + h*32 + y)*1024 + xq*32;
    #pragma unroll
    for (int w = 0; w < 16; w++) {
        float2 v = unpack2(vacc[w]);
        ob[2*w]   = v.x * inv;
        ob[2*w+1] = v.y * inv;
    }
}

// ---------------------------------------------------------------------------
// Kernel 3: 1x1 projection of attn maps -> d_out channels [256,512).
// ---------------------------------------------------------------------------
__global__ void __launch_bounds__(256) k_proj(
    const float* __restrict__ attn_w, const float* __restrict__ attn_b,
    float* __restrict__ out)
{
    __shared__ float As[32*128];     // [ci][pp]
    __shared__ float Ws[128*32];     // [co][ci]
    const int t = threadIdx.x;
    const int ptile = blockIdx.x;    // 0..7
    const int cotile = blockIdx.y;   // 0..1
    const int n = blockIdx.z;
    const int pg = t & 31, cg = t >> 5;

    float acc[16][4];
    #pragma unroll
    for (int u = 0; u < 16; u++)
        #pragma unroll
        for (int j = 0; j < 4; j++) acc[u][j] = 0.f;

    #pragma unroll 1
    for (int ci0 = 0; ci0 < 256; ci0 += 32) {
        __syncthreads();
        #pragma unroll
        for (int r = 0; r < 16; r++) {
            int e = r*256 + t;
            int ci = e >> 7, pp = e & 127;
            As[e] = g_attn[(n*256 + ci0 + ci)*1024 + ptile*128 + pp];
        }
        #pragma unroll
        for (int r = 0; r < 16; r++) {
            int e = r*256 + t;
            int co = e >> 5, ci = e & 31;
            Ws[e] = attn_w[(cotile*128 + co)*256 + ci0 + ci];
        }
        __syncthreads();
        #pragma unroll 8
        for (int ci = 0; ci < 32; ci++) {
            float a0 = As[ci*128 + pg];
            float a1 = As[ci*128 + pg + 32];
            float a2 = As[ci*128 + pg + 64];
            float a3 = As[ci*128 + pg + 96];
            #pragma unroll
            for (int u = 0; u < 16; u++) {
                float w = Ws[(cg*16 + u)*32 + ci];
                acc[u][0] += w*a0; acc[u][1] += w*a1;
                acc[u][2] += w*a2; acc[u][3] += w*a3;
            }
        }
    }

    #pragma unroll
    for (int u = 0; u < 16; u++) {
        int co = cotile*128 + cg*16 + u;
        float b = attn_b[co];
        #pragma unroll
        for (int j = 0; j < 4; j++) {
            int p = ptile*128 + pg + 32*j;
            out[(n*512 + 256 + co)*1024 + p] = acc[u][j] + b;
        }
    }
}

// ---------------------------------------------------------------------------
extern "C" void kernel_launch(void* const* d_in, const int* in_sizes, int n_in,
                              void* d_out, int out_size)
{
    const float* x          = (const float*)d_in[0];
    const float* conv_w     = (const float*)d_in[1];
    const float* conv_b     = (const float*)d_in[2];
    const float* q_w        = (const float*)d_in[3];
    const float* q_b        = (const float*)d_in[4];
    const float* k_w        = (const float*)d_in[5];
    const float* k_b        = (const float*)d_in[6];
    const float* v_w        = (const float*)d_in[7];
    const float* v_b        = (const float*)d_in[8];
    const float* attn_w     = (const float*)d_in[9];
    const float* attn_b     = (const float*)d_in[10];
    const float* width_mat  = (const float*)d_in[11];
    const float* height_mat = (const float*)d_in[12];
    float* out = (float*)d_out;

    k_conv<<<dim3(8, 16, 8), 128>>>(x, conv_w, conv_b, q_w, q_b,
                                    k_w, k_b, v_w, v_b, out);

    cudaFuncSetAttribute(k_attn, cudaFuncAttributeMaxDynamicSharedMemorySize,
                         SM2_FLOATS * (int)sizeof(float));
    k_attn<<<dim3(8, 64), 128, SM2_FLOATS * sizeof(float)>>>(height_mat, width_mat);

    k_proj<<<dim3(8, 2, 8), 256>>>(attn_w, attn_b, out);
}